// round 3
// baseline (speedup 1.0000x reference)
#include <cuda_runtime.h>
#include <cstdint>

#define Bn   8
#define Cn   256
#define Kn   9
#define Hn   64
#define Wn   64
#define HWn  (Hn*Wn)       // 4096
#define NPIX (Bn*HWn)      // 32768

// ---- scratch (device globals; no allocation allowed) ----
__device__ float g_key_t[(size_t)Bn*HWn*Cn];   // [B][HW][C] transposed key_layer
__device__ float g_s[(size_t)Bn*HWn*Cn];       // aggregated sampled raw-key features
__device__ float g_aw[Bn*Kn*HWn];
__device__ float g_dy[Bn*Kn*HWn];
__device__ float g_dx[Bn*Kn*HWn];
__device__ float g_g[Bn*HWn];                  // bias weight-sum per pixel

// ============================================================
// K1: transpose key_layer [B,C,HW] -> g_key_t [B,HW,C]
// ============================================================
__global__ void k_transpose(const float* __restrict__ key) {
    __shared__ float t[32][33];
    int b   = blockIdx.z;
    int hw0 = blockIdx.x * 32;
    int c0  = blockIdx.y * 32;
    int tx = threadIdx.x, ty = threadIdx.y;
    const float* src = key + (size_t)b * Cn * HWn;
    #pragma unroll
    for (int i = 0; i < 4; i++)
        t[ty + i*8][tx] = src[(size_t)(c0 + ty + i*8) * HWn + hw0 + tx];
    __syncthreads();
    float* dst = g_key_t + (size_t)b * HWn * Cn;
    #pragma unroll
    for (int i = 0; i < 4; i++)
        dst[(size_t)(hw0 + ty + i*8) * Cn + c0 + tx] = t[tx][ty + i*8];
}

// ============================================================
// K2: per-pixel params: 28 conv1x1 outputs (attn 9, mask 9, off 10),
//     both softmaxes, store aw/dy/dx.
// ============================================================
__global__ void k_params(const float* __restrict__ query,
                         const float* __restrict__ gmb,
                         const float* __restrict__ b_attn,
                         const float* __restrict__ b_mask,
                         const float* __restrict__ b_off,
                         const float* __restrict__ w_attn,
                         const float* __restrict__ w_mask,
                         const float* __restrict__ w_off,
                         const unsigned* __restrict__ temp_raw) {
    __shared__ float4 sW[28*64];   // rows 0..8 attn, 9..17 mask, 18..27 off[0..9]
    __shared__ float  sB[28];
    int tid = threadIdx.x;
    for (int i = tid; i < 576; i += 256) sW[i]        = ((const float4*)w_attn)[i];
    for (int i = tid; i < 576; i += 256) sW[576 + i]  = ((const float4*)w_mask)[i];
    for (int i = tid; i < 640; i += 256) sW[1152 + i] = ((const float4*)w_off)[i];
    if (tid < 9)  { sB[tid] = b_attn[tid]; sB[9 + tid] = b_mask[tid]; }
    if (tid < 10) sB[18 + tid] = b_off[tid];
    __syncthreads();

    int idx = blockIdx.x * 256 + tid;
    int b  = idx >> 12;
    int hw = idx & (HWn - 1);

    const float* q = query + (size_t)b * Cn * HWn + hw;
    float acc[28];
    #pragma unroll
    for (int r = 0; r < 28; r++) acc[r] = 0.f;

    for (int c4 = 0; c4 < 64; c4++) {
        float q0 = q[(c4*4 + 0) * HWn];
        float q1 = q[(c4*4 + 1) * HWn];
        float q2 = q[(c4*4 + 2) * HWn];
        float q3 = q[(c4*4 + 3) * HWn];
        #pragma unroll
        for (int r = 0; r < 28; r++) {
            float4 w = sW[r*64 + c4];
            acc[r] += q0*w.x + q1*w.y + q2*w.z + q3*w.w;
        }
    }

    // temp (dataset value is the python int 1; accept int32/int64/float encodings)
    unsigned lo = temp_raw[0];
    float t;
    if      (lo == 1u)           t = 1.f;   // int32 / int64 low word
    else if (lo == 0x3F800000u)  t = 1.f;   // float32 1.0
    else if (lo == 0u)           t = 1.f;   // double 1.0 low word
    else                         t = __uint_as_float(lo);
    float invt = 1.f / t;

    // hard_mask = softmax((mask + gumbel)/t)
    float mv[9]; float mx = -3.4e38f;
    #pragma unroll
    for (int k = 0; k < 9; k++) {
        float gk = gmb[(size_t)(b*Kn + k) * HWn + hw];
        mv[k] = (acc[9 + k] + sB[9 + k] + gk) * invt;
        mx = fmaxf(mx, mv[k]);
    }
    float sum = 0.f;
    #pragma unroll
    for (int k = 0; k < 9; k++) { mv[k] = expf(mv[k] - mx); sum += mv[k]; }
    float rs = 1.f / sum;

    // aw = softmax(attn * hard_mask)
    float z[9]; float mx2 = -3.4e38f;
    #pragma unroll
    for (int k = 0; k < 9; k++) {
        z[k] = (acc[k] + sB[k]) * (mv[k] * rs);
        mx2 = fmaxf(mx2, z[k]);
    }
    float sum2 = 0.f;
    #pragma unroll
    for (int k = 0; k < 9; k++) { z[k] = expf(z[k] - mx2); sum2 += z[k]; }
    float rs2 = 1.f / sum2;

    #pragma unroll
    for (int k = 0; k < 9; k++) {
        int o = (b*Kn + k) * HWn + hw;
        g_aw[o] = z[k] * rs2;
        g_dy[o] = acc[18 + k] + sB[18 + k];   // offset channel k
        g_dx[o] = acc[19 + k] + sB[19 + k];   // offset channel k+1 (overlapping slice!)
    }
}

// ============================================================
// K3: gather — s[b,hw,c] = sum_k aw_k * bilinear_k(key_t[b,:,:,c])
//     g[b,hw]  = sum_k aw_k * sum_j w_j*valid_j
// One block = one image row (64 pixels), thread = channel.
// ============================================================
__global__ void k_gather() {
    __shared__ float2 wo[64][36];   // .x = folded weight, .y = int bits of element offset
    int y   = blockIdx.x;
    int b   = blockIdx.y;
    int tid = threadIdx.x;

    for (int i = tid; i < 64*9; i += 256) {
        int p = i / 9, k = i % 9;
        int hw = y*Wn + p;
        int o  = (b*Kn + k) * HWn + hw;
        float aw = g_aw[o];
        float dy = g_dy[o], dx = g_dx[o];
        float py = (float)y + dy;
        float px = (float)p + dx;
        float y0f = floorf(py), x0f = floorf(px);
        float wy = py - y0f, wx = px - x0f;
        int y0 = (int)y0f, x0 = (int)x0f;
        int y1 = y0 + 1,   x1 = x0 + 1;
        float w00 = (1.f-wy)*(1.f-wx)*aw;
        float w01 = (1.f-wy)*wx*aw;
        float w10 = wy*(1.f-wx)*aw;
        float w11 = wy*wx*aw;
        int yc0 = min(max(y0,0),Hn-1), yc1 = min(max(y1,0),Hn-1);
        int xc0 = min(max(x0,0),Wn-1), xc1 = min(max(x1,0),Wn-1);
        bool vy0 = (y0 >= 0) & (y0 < Hn);
        bool vy1 = (y1 >= 0) & (y1 < Hn);
        bool vx0 = (x0 >= 0) & (x0 < Wn);
        bool vx1 = (x1 >= 0) & (x1 < Wn);
        wo[p][k*4+0] = make_float2((vy0 && vx0) ? w00 : 0.f, __int_as_float((yc0*Wn + xc0)*Cn));
        wo[p][k*4+1] = make_float2((vy0 && vx1) ? w01 : 0.f, __int_as_float((yc0*Wn + xc1)*Cn));
        wo[p][k*4+2] = make_float2((vy1 && vx0) ? w10 : 0.f, __int_as_float((yc1*Wn + xc0)*Cn));
        wo[p][k*4+3] = make_float2((vy1 && vx1) ? w11 : 0.f, __int_as_float((yc1*Wn + xc1)*Cn));
    }
    __syncthreads();

    if (tid < 64) {
        float gs = 0.f;
        #pragma unroll
        for (int j = 0; j < 36; j++) gs += wo[tid][j].x;
        g_g[b*HWn + y*Wn + tid] = gs;
    }

    int c = tid;
    const float* kb = g_key_t + (size_t)b * HWn * Cn;
    for (int p = 0; p < 64; p++) {
        float acc = 0.f;
        #pragma unroll
        for (int j = 0; j < 36; j++) {
            float2 w = wo[p][j];
            acc += w.x * kb[__float_as_int(w.y) + c];
        }
        g_s[((size_t)b*HWn + y*Wn + p) * Cn + c] = acc;
    }
}

// ============================================================
// K4: out[b,o,hw] = sum_c W[o,c]*s[b,hw,c] + b_refer[o]*g[b,hw]
// 128x128 block tile, 8x8 thread tile, k-step 8, sw-pipelined loads.
// ============================================================
__global__ void __launch_bounds__(256, 2)
k_gemm(const float* __restrict__ Wr, const float* __restrict__ bref,
       float* __restrict__ out) {
    __shared__ __align__(16) float As[8][132];
    __shared__ __align__(16) float Bs[8][132];
    int b  = blockIdx.z;
    int p0 = blockIdx.x * 128;   // pixel tile
    int o0 = blockIdx.y * 128;   // output-channel tile
    int tid = threadIdx.x;
    int tx = tid & 15, ty = tid >> 4;
    int lr = tid >> 1;           // 0..127
    int lc = (tid & 1) * 4;      // 0 or 4
    const float* Sb = g_s + (size_t)b * HWn * Cn;

    float acc[8][8];
    #pragma unroll
    for (int i = 0; i < 8; i++)
        #pragma unroll
        for (int j = 0; j < 8; j++) acc[i][j] = 0.f;

    float4 a4 = *(const float4*)&Wr[(o0 + lr)*Cn + lc];
    float4 b4 = *(const float4*)&Sb[(size_t)(p0 + lr)*Cn + lc];

    for (int c0 = 0; c0 < Cn; c0 += 8) {
        As[lc+0][lr] = a4.x; As[lc+1][lr] = a4.y; As[lc+2][lr] = a4.z; As[lc+3][lr] = a4.w;
        Bs[lc+0][lr] = b4.x; Bs[lc+1][lr] = b4.y; Bs[lc+2][lr] = b4.z; Bs[lc+3][lr] = b4.w;
        __syncthreads();
        if (c0 + 8 < Cn) {
            a4 = *(const float4*)&Wr[(o0 + lr)*Cn + c0 + 8 + lc];
            b4 = *(const float4*)&Sb[(size_t)(p0 + lr)*Cn + c0 + 8 + lc];
        }
        #pragma unroll
        for (int cc = 0; cc < 8; cc++) {
            float af[8], bf[8];
            *(float4*)&af[0] = *(const float4*)&As[cc][ty*8];
            *(float4*)&af[4] = *(const float4*)&As[cc][ty*8 + 4];
            *(float4*)&bf[0] = *(const float4*)&Bs[cc][tx*8];
            *(float4*)&bf[4] = *(const float4*)&Bs[cc][tx*8 + 4];
            #pragma unroll
            for (int i = 0; i < 8; i++)
                #pragma unroll
                for (int j = 0; j < 8; j++)
                    acc[i][j] += af[i] * bf[j];
        }
        __syncthreads();
    }

    int hwb = p0 + tx*8;
    float gv[8];
    #pragma unroll
    for (int j = 0; j < 8; j++) gv[j] = g_g[b*HWn + hwb + j];
    #pragma unroll
    for (int i = 0; i < 8; i++) {
        int o = o0 + ty*8 + i;
        float bb = bref[o];
        float* orow = out + ((size_t)b*Cn + o) * HWn + hwb;
        float4 r0, r1;
        r0.x = acc[i][0] + bb*gv[0]; r0.y = acc[i][1] + bb*gv[1];
        r0.z = acc[i][2] + bb*gv[2]; r0.w = acc[i][3] + bb*gv[3];
        r1.x = acc[i][4] + bb*gv[4]; r1.y = acc[i][5] + bb*gv[5];
        r1.z = acc[i][6] + bb*gv[6]; r1.w = acc[i][7] + bb*gv[7];
        *(float4*)&orow[0] = r0;
        *(float4*)&orow[4] = r1;
    }
}

// ============================================================
extern "C" void kernel_launch(void* const* d_in, const int* in_sizes, int n_in,
                              void* d_out, int out_size) {
    const float* query   = (const float*)d_in[0];
    const float* key     = (const float*)d_in[1];
    const float* gmb     = (const float*)d_in[2];
    const float* w_refer = (const float*)d_in[3];
    const float* b_refer = (const float*)d_in[4];
    const float* w_attn  = (const float*)d_in[5];
    const float* b_attn  = (const float*)d_in[6];
    const float* w_mask  = (const float*)d_in[7];
    const float* b_mask  = (const float*)d_in[8];
    const float* w_off   = (const float*)d_in[9];
    const float* b_off   = (const float*)d_in[10];
    const unsigned* temp = (const unsigned*)d_in[11];
    float* out = (float*)d_out;

    k_transpose<<<dim3(HWn/32, Cn/32, Bn), dim3(32, 8)>>>(key);
    k_params<<<NPIX/256, 256>>>(query, gmb, b_attn, b_mask, b_off,
                                w_attn, w_mask, w_off, temp);
    k_gather<<<dim3(Hn, Bn), 256>>>();
    k_gemm<<<dim3(HWn/128, Cn/128, Bn), 256>>>(w_refer, b_refer, out);
}

// round 5
// speedup vs baseline: 1.2678x; 1.2678x over previous
#include <cuda_runtime.h>
#include <cuda_bf16.h>
#include <cstdint>

#define Bn   8
#define Cn   256
#define Kn   9
#define Hn   64
#define Wn   64
#define HWn  (Hn*Wn)       // 4096
#define NPIX (Bn*HWn)      // 32768

// ---- scratch (device globals; no allocation allowed) ----
__device__ float g_key_t[(size_t)Bn*HWn*Cn];          // [B][HW][C] transposed key
__device__ __nv_bfloat16 g_sh[(size_t)NPIX*Cn];       // sampled features, bf16 hi
__device__ __nv_bfloat16 g_sl[(size_t)NPIX*Cn];       // sampled features, bf16 lo
__device__ __nv_bfloat16 g_wh[Cn*Cn];                 // w_refer hi
__device__ __nv_bfloat16 g_wl[Cn*Cn];                 // w_refer lo
__device__ float g_aw[Bn*Kn*HWn];
__device__ float g_dy[Bn*Kn*HWn];
__device__ float g_dx[Bn*Kn*HWn];
__device__ float g_g[Bn*HWn];                          // bias weight-sum per pixel

// ================= helpers =================
__device__ __forceinline__ uint32_t smem_u32(const void* p) {
    uint32_t a;
    asm("{ .reg .u64 t; cvta.to.shared.u64 t, %1; cvt.u32.u64 %0, t; }" : "=r"(a) : "l"(p));
    return a;
}
__device__ __forceinline__ uint32_t lds32(uint32_t a) {
    uint32_t v;
    asm volatile("ld.shared.b32 %0, [%1];" : "=r"(v) : "r"(a));
    return v;
}
__device__ __forceinline__ void sts128(uint32_t a, uint4 v) {
    asm volatile("st.shared.v4.b32 [%0], {%1, %2, %3, %4};"
                 :: "r"(a), "r"(v.x), "r"(v.y), "r"(v.z), "r"(v.w) : "memory");
}
__device__ __forceinline__ void ldmatrix_x4(uint32_t& r0, uint32_t& r1,
                                            uint32_t& r2, uint32_t& r3, uint32_t a) {
    asm volatile("ldmatrix.sync.aligned.m8n8.x4.shared.b16 {%0,%1,%2,%3}, [%4];"
                 : "=r"(r0), "=r"(r1), "=r"(r2), "=r"(r3) : "r"(a));
}
__device__ __forceinline__ void mma16816(float* c, uint32_t a0, uint32_t a1,
                                         uint32_t a2, uint32_t a3,
                                         uint32_t b0, uint32_t b1) {
    asm volatile(
        "mma.sync.aligned.m16n8k16.row.col.f32.bf16.bf16.f32 "
        "{%0,%1,%2,%3}, {%4,%5,%6,%7}, {%8,%9}, {%0,%1,%2,%3};"
        : "+f"(c[0]), "+f"(c[1]), "+f"(c[2]), "+f"(c[3])
        : "r"(a0), "r"(a1), "r"(a2), "r"(a3), "r"(b0), "r"(b1));
}

// ============================================================
// K1: transpose key_layer [B,C,HW] -> g_key_t [B,HW,C]
// ============================================================
__global__ void k_transpose(const float* __restrict__ key) {
    __shared__ float t[32][33];
    int b   = blockIdx.z;
    int hw0 = blockIdx.x * 32;
    int c0  = blockIdx.y * 32;
    int tx = threadIdx.x, ty = threadIdx.y;
    const float* src = key + (size_t)b * Cn * HWn;
    #pragma unroll
    for (int i = 0; i < 4; i++)
        t[ty + i*8][tx] = src[(size_t)(c0 + ty + i*8) * HWn + hw0 + tx];
    __syncthreads();
    float* dst = g_key_t + (size_t)b * HWn * Cn;
    #pragma unroll
    for (int i = 0; i < 4; i++)
        dst[(size_t)(hw0 + ty + i*8) * Cn + c0 + tx] = t[tx][ty + i*8];
}

// ============================================================
// K2: per-pixel params: 28 conv1x1 rows, both softmaxes
// ============================================================
__global__ void k_params(const float* __restrict__ query,
                         const float* __restrict__ gmb,
                         const float* __restrict__ b_attn,
                         const float* __restrict__ b_mask,
                         const float* __restrict__ b_off,
                         const float* __restrict__ w_attn,
                         const float* __restrict__ w_mask,
                         const float* __restrict__ w_off,
                         const unsigned* __restrict__ temp_raw) {
    __shared__ float4 sW[28*64];
    __shared__ float  sB[28];
    int tid = threadIdx.x;
    for (int i = tid; i < 576; i += 256) sW[i]        = ((const float4*)w_attn)[i];
    for (int i = tid; i < 576; i += 256) sW[576 + i]  = ((const float4*)w_mask)[i];
    for (int i = tid; i < 640; i += 256) sW[1152 + i] = ((const float4*)w_off)[i];
    if (tid < 9)  { sB[tid] = b_attn[tid]; sB[9 + tid] = b_mask[tid]; }
    if (tid < 10) sB[18 + tid] = b_off[tid];
    __syncthreads();

    int idx = blockIdx.x * 256 + tid;
    int b  = idx >> 12;
    int hw = idx & (HWn - 1);

    const float* q = query + (size_t)b * Cn * HWn + hw;
    float acc[28];
    #pragma unroll
    for (int r = 0; r < 28; r++) acc[r] = 0.f;

    for (int c4 = 0; c4 < 64; c4++) {
        float q0 = q[(c4*4 + 0) * HWn];
        float q1 = q[(c4*4 + 1) * HWn];
        float q2 = q[(c4*4 + 2) * HWn];
        float q3 = q[(c4*4 + 3) * HWn];
        #pragma unroll
        for (int r = 0; r < 28; r++) {
            float4 w = sW[r*64 + c4];
            acc[r] += q0*w.x + q1*w.y + q2*w.z + q3*w.w;
        }
    }

    unsigned lo = temp_raw[0];
    float t;
    if      (lo == 1u)           t = 1.f;
    else if (lo == 0x3F800000u)  t = 1.f;
    else if (lo == 0u)           t = 1.f;
    else                         t = __uint_as_float(lo);
    float invt = 1.f / t;

    float mv[9]; float mx = -3.4e38f;
    #pragma unroll
    for (int k = 0; k < 9; k++) {
        float gk = gmb[(size_t)(b*Kn + k) * HWn + hw];
        mv[k] = (acc[9 + k] + sB[9 + k] + gk) * invt;
        mx = fmaxf(mx, mv[k]);
    }
    float sum = 0.f;
    #pragma unroll
    for (int k = 0; k < 9; k++) { mv[k] = expf(mv[k] - mx); sum += mv[k]; }
    float rs = 1.f / sum;

    float z[9]; float mx2 = -3.4e38f;
    #pragma unroll
    for (int k = 0; k < 9; k++) {
        z[k] = (acc[k] + sB[k]) * (mv[k] * rs);
        mx2 = fmaxf(mx2, z[k]);
    }
    float sum2 = 0.f;
    #pragma unroll
    for (int k = 0; k < 9; k++) { z[k] = expf(z[k] - mx2); sum2 += z[k]; }
    float rs2 = 1.f / sum2;

    #pragma unroll
    for (int k = 0; k < 9; k++) {
        int o = (b*Kn + k) * HWn + hw;
        g_aw[o] = z[k] * rs2;
        g_dy[o] = acc[18 + k] + sB[18 + k];
        g_dx[o] = acc[19 + k] + sB[19 + k];
    }
}

// ============================================================
// K3: split w_refer into bf16 hi/lo
// ============================================================
__global__ void k_wsplit(const float* __restrict__ w) {
    int i = blockIdx.x * 256 + threadIdx.x;
    float v = w[i];
    __nv_bfloat16 h = __float2bfloat16(v);
    g_wh[i] = h;
    g_wl[i] = __float2bfloat16(v - __bfloat162float(h));
}

// ============================================================
// K4: gather with tap dedup; outputs s as bf16 hi/lo
// ============================================================
__global__ void k_gather() {
    __shared__ int   s_idx[64][40];
    __shared__ float s_w[64][40];
    __shared__ int   s_cnt[64];
    int y   = blockIdx.x;
    int b   = blockIdx.y;
    int tid = threadIdx.x;

    if (tid < 64) {
        int p = tid, hw = y*Wn + p;
        float gs = 0.f; int n = 0;
        #pragma unroll
        for (int k = 0; k < 9; k++) {
            int o = (b*Kn + k) * HWn + hw;
            float aw = g_aw[o];
            float dy = g_dy[o], dx = g_dx[o];
            float py = (float)y + dy;
            float px = (float)p + dx;
            float y0f = floorf(py), x0f = floorf(px);
            float wy = py - y0f, wx = px - x0f;
            int y0 = (int)y0f, x0 = (int)x0f;
            float ws[4] = {(1.f-wy)*(1.f-wx), (1.f-wy)*wx, wy*(1.f-wx), wy*wx};
            int   yy[4] = {y0, y0, y0+1, y0+1};
            int   xx[4] = {x0, x0+1, x0, x0+1};
            #pragma unroll
            for (int t = 0; t < 4; t++) {
                bool v = (yy[t] >= 0) & (yy[t] < Hn) & (xx[t] >= 0) & (xx[t] < Wn);
                float w = ws[t] * aw;
                if (!v || w == 0.f) continue;
                int idx = (yy[t]*Wn + xx[t]) * Cn;
                gs += w;
                int j = 0;
                for (; j < n; j++)
                    if (s_idx[p][j] == idx) { s_w[p][j] += w; break; }
                if (j == n) { s_idx[p][n] = idx; s_w[p][n] = w; n++; }
            }
        }
        s_cnt[p] = n;
        g_g[b*HWn + hw] = gs;
    }
    __syncthreads();

    int c4 = tid & 63;          // float4 channel group
    int pg = tid >> 6;          // pixel phase (0..3)
    const float4* kb = (const float4*)(g_key_t + (size_t)b * HWn * Cn);
    for (int p = pg; p < 64; p += 4) {
        int n = s_cnt[p];
        float4 acc = make_float4(0.f, 0.f, 0.f, 0.f);
        for (int j = 0; j < n; j++) {
            float w = s_w[p][j];
            float4 v = kb[(s_idx[p][j] >> 2) + c4];
            acc.x += w*v.x; acc.y += w*v.y; acc.z += w*v.z; acc.w += w*v.w;
        }
        size_t base = ((size_t)(b*HWn + y*Wn + p)) * Cn + c4*4;
        __nv_bfloat16 hx = __float2bfloat16(acc.x);
        __nv_bfloat16 hy = __float2bfloat16(acc.y);
        __nv_bfloat16 hz = __float2bfloat16(acc.z);
        __nv_bfloat16 hw4 = __float2bfloat16(acc.w);
        __nv_bfloat16 lx = __float2bfloat16(acc.x - __bfloat162float(hx));
        __nv_bfloat16 ly = __float2bfloat16(acc.y - __bfloat162float(hy));
        __nv_bfloat16 lz = __float2bfloat16(acc.z - __bfloat162float(hz));
        __nv_bfloat16 lw = __float2bfloat16(acc.w - __bfloat162float(hw4));
        __nv_bfloat162 h0 = __halves2bfloat162(hx, hy);
        __nv_bfloat162 h1 = __halves2bfloat162(hz, hw4);
        __nv_bfloat162 l0 = __halves2bfloat162(lx, ly);
        __nv_bfloat162 l1 = __halves2bfloat162(lz, lw);
        uint2 uh, ul;
        uh.x = *(uint32_t*)&h0; uh.y = *(uint32_t*)&h1;
        ul.x = *(uint32_t*)&l0; ul.y = *(uint32_t*)&l1;
        *(uint2*)&g_sh[base] = uh;
        *(uint2*)&g_sl[base] = ul;
    }
}

// ============================================================
// K5: mma.sync bf16 split GEMM (HMMA.16816, base sm_100-compatible)
//   D[o,p] = Wh.Sh^T + Wl.Sh^T + Wh.Sl^T  (virtual K = 768)
//   CTA: 128x128, 8 warps (2x4), warp: 64x32, k-chunk 32.
// SMEM pitch 80B (40 bf16) -> bank-conflict-free ldmatrix.
// ============================================================
#define PITCH_B 80
#define NCHUNK  24   // 3 segments * (256/32)

__global__ void __launch_bounds__(256)
k_gemm_mma(const float* __restrict__ bref, float* __restrict__ out) {
    __shared__ __align__(16) __nv_bfloat16 sA[128*40];
    __shared__ __align__(16) __nv_bfloat16 sB[128*40];

    int tid = threadIdx.x, wid = tid >> 5, lane = tid & 31;
    int p0 = blockIdx.x * 128;
    int o0 = blockIdx.y * 128;
    int bz = blockIdx.z;
    int wr = wid >> 2;          // 0..1 (m)
    int wn = wid & 3;           // 0..3 (n)

    const __nv_bfloat16* Aseg[3] = {g_wh, g_wl, g_wh};
    const __nv_bfloat16* Bseg[3] = {g_sh, g_sh, g_sl};

    uint32_t sA_b = smem_u32(sA);
    uint32_t sB_b = smem_u32(sB);

    float acc[4][4][4];
    #pragma unroll
    for (int i = 0; i < 4; i++)
        #pragma unroll
        for (int j = 0; j < 4; j++)
            #pragma unroll
            for (int r = 0; r < 4; r++) acc[i][j][r] = 0.f;

    // global->reg staging roles
    int lr = tid & 127;         // row 0..127
    int lh = tid >> 7;          // 0/1: which pair of uint4 in the 64B row
    uint4 ra0, ra1, rb0, rb1;

    // ldmatrix source addresses (per m-tile, per k16 step)
    // lane l -> row (l>>3 &1)*8 + (l&7) within 16-row block, col block (l>>4)*16B
    int lm_row = ((lane >> 3) & 1) * 8 + (lane & 7);
    int lm_col = (lane >> 4) * 16;

    // B fragment lds addresses
    int bn_row = lane >> 2;     // 0..7 within n-tile
    int bn_col = (lane & 3) * 4;

    // ---- preload chunk 0 ----
    {
        const uint4* Ag = (const uint4*)(Aseg[0] + (size_t)(o0 + lr)*Cn);
        const uint4* Bg = (const uint4*)(Bseg[0] + ((size_t)bz*HWn + p0 + lr)*Cn);
        ra0 = Ag[lh*2]; ra1 = Ag[lh*2+1];
        rb0 = Bg[lh*2]; rb1 = Bg[lh*2+1];
    }
    sts128(sA_b + lr*PITCH_B + (lh*2+0)*16, ra0);
    sts128(sA_b + lr*PITCH_B + (lh*2+1)*16, ra1);
    sts128(sB_b + lr*PITCH_B + (lh*2+0)*16, rb0);
    sts128(sB_b + lr*PITCH_B + (lh*2+1)*16, rb1);
    __syncthreads();

    for (int ch = 0; ch < NCHUNK; ch++) {
        // prefetch next chunk into regs
        if (ch + 1 < NCHUNK) {
            int seg = (ch + 1) >> 3;
            int c0  = ((ch + 1) & 7) * 32;
            const uint4* Ag = (const uint4*)(Aseg[seg] + (size_t)(o0 + lr)*Cn + c0);
            const uint4* Bg = (const uint4*)(Bseg[seg] + ((size_t)bz*HWn + p0 + lr)*Cn + c0);
            ra0 = Ag[lh*2]; ra1 = Ag[lh*2+1];
            rb0 = Bg[lh*2]; rb1 = Bg[lh*2+1];
        }

        // MMA over current smem tile: 2 k16 sub-steps
        #pragma unroll
        for (int ks = 0; ks < 2; ks++) {
            uint32_t bf[4][2];
            #pragma unroll
            for (int nt = 0; nt < 4; nt++) {
                uint32_t ba = sB_b + (wn*32 + nt*8 + bn_row)*PITCH_B + bn_col + ks*32;
                bf[nt][0] = lds32(ba);
                bf[nt][1] = lds32(ba + 16);
            }
            #pragma unroll
            for (int mt = 0; mt < 4; mt++) {
                uint32_t a0, a1, a2, a3;
                uint32_t aa = sA_b + (wr*64 + mt*16 + lm_row)*PITCH_B + lm_col + ks*32;
                ldmatrix_x4(a0, a1, a2, a3, aa);
                #pragma unroll
                for (int nt = 0; nt < 4; nt++)
                    mma16816(acc[mt][nt], a0, a1, a2, a3, bf[nt][0], bf[nt][1]);
            }
        }

        if (ch + 1 < NCHUNK) {
            __syncthreads();   // all warps done reading current tile
            sts128(sA_b + lr*PITCH_B + (lh*2+0)*16, ra0);
            sts128(sA_b + lr*PITCH_B + (lh*2+1)*16, ra1);
            sts128(sB_b + lr*PITCH_B + (lh*2+0)*16, rb0);
            sts128(sB_b + lr*PITCH_B + (lh*2+1)*16, rb1);
            __syncthreads();
        }
    }

    // ---- epilogue: D[m16n8] regs: c0=D[r][c], c1=D[r][c+1], c2=D[r+8][c], c3 ----
    int mrow = lane >> 2;          // 0..7
    int ncol = (lane & 3) * 2;     // 0,2,4,6
    #pragma unroll
    for (int mt = 0; mt < 4; mt++) {
        int o = o0 + wr*64 + mt*16 + mrow;
        float bb0 = bref[o], bb1 = bref[o + 8];
        #pragma unroll
        for (int nt = 0; nt < 4; nt++) {
            int p = p0 + wn*32 + nt*8 + ncol;
            float2 gg = *(const float2*)&g_g[bz*HWn + p];
            float2 r0, r1;
            r0.x = acc[mt][nt][0] + bb0*gg.x;
            r0.y = acc[mt][nt][1] + bb0*gg.y;
            r1.x = acc[mt][nt][2] + bb1*gg.x;
            r1.y = acc[mt][nt][3] + bb1*gg.y;
            *(float2*)&out[((size_t)(bz*Cn + o))     * HWn + p] = r0;
            *(float2*)&out[((size_t)(bz*Cn + o + 8)) * HWn + p] = r1;
        }
    }
}

// ============================================================
extern "C" void kernel_launch(void* const* d_in, const int* in_sizes, int n_in,
                              void* d_out, int out_size) {
    const float* query   = (const float*)d_in[0];
    const float* key     = (const float*)d_in[1];
    const float* gmb     = (const float*)d_in[2];
    const float* w_refer = (const float*)d_in[3];
    const float* b_refer = (const float*)d_in[4];
    const float* w_attn  = (const float*)d_in[5];
    const float* b_attn  = (const float*)d_in[6];
    const float* w_mask  = (const float*)d_in[7];
    const float* b_mask  = (const float*)d_in[8];
    const float* w_off   = (const float*)d_in[9];
    const float* b_off   = (const float*)d_in[10];
    const unsigned* temp = (const unsigned*)d_in[11];
    float* out = (float*)d_out;

    k_transpose<<<dim3(HWn/32, Cn/32, Bn), dim3(32, 8)>>>(key);
    k_params<<<NPIX/256, 256>>>(query, gmb, b_attn, b_mask, b_off,
                                w_attn, w_mask, w_off, temp);
    k_wsplit<<<Cn*Cn/256, 256>>>(w_refer);
    k_gather<<<dim3(Hn, Bn), 256>>>();
    k_gemm_mma<<<dim3(HWn/128, Cn/128, Bn), 256>>>(b_refer, out);
}

// round 6
// speedup vs baseline: 1.8437x; 1.4543x over previous
#include <cuda_runtime.h>
#include <cuda_bf16.h>
#include <cstdint>

#define Bn   8
#define Cn   256
#define Kn   9
#define Hn   64
#define Wn   64
#define HWn  (Hn*Wn)       // 4096
#define NPIX (Bn*HWn)      // 32768

// ---- scratch (device globals; no allocation allowed) ----
__device__ float g_key_t[(size_t)Bn*HWn*Cn];          // [B][HW][C] transposed key
__device__ __nv_bfloat16 g_sh[(size_t)NPIX*Cn];       // sampled features, bf16 hi
__device__ __nv_bfloat16 g_sl[(size_t)NPIX*Cn];       // sampled features, bf16 lo
__device__ __nv_bfloat16 g_wh[Cn*Cn];                 // w_refer hi
__device__ __nv_bfloat16 g_wl[Cn*Cn];                 // w_refer lo
__device__ float g_aw[Bn*Kn*HWn];
__device__ float g_dy[Bn*Kn*HWn];
__device__ float g_dx[Bn*Kn*HWn];
__device__ float g_g[Bn*HWn];                          // bias weight-sum per pixel

// ================= helpers =================
__device__ __forceinline__ uint32_t smem_u32(const void* p) {
    uint32_t a;
    asm("{ .reg .u64 t; cvta.to.shared.u64 t, %1; cvt.u32.u64 %0, t; }" : "=r"(a) : "l"(p));
    return a;
}
__device__ __forceinline__ uint32_t lds32(uint32_t a) {
    uint32_t v;
    asm volatile("ld.shared.b32 %0, [%1];" : "=r"(v) : "r"(a));
    return v;
}
__device__ __forceinline__ void ldmatrix_x4(uint32_t& r0, uint32_t& r1,
                                            uint32_t& r2, uint32_t& r3, uint32_t a) {
    asm volatile("ldmatrix.sync.aligned.m8n8.x4.shared.b16 {%0,%1,%2,%3}, [%4];"
                 : "=r"(r0), "=r"(r1), "=r"(r2), "=r"(r3) : "r"(a));
}
__device__ __forceinline__ void mma16816(float* c, uint32_t a0, uint32_t a1,
                                         uint32_t a2, uint32_t a3,
                                         uint32_t b0, uint32_t b1) {
    asm volatile(
        "mma.sync.aligned.m16n8k16.row.col.f32.bf16.bf16.f32 "
        "{%0,%1,%2,%3}, {%4,%5,%6,%7}, {%8,%9}, {%0,%1,%2,%3};"
        : "+f"(c[0]), "+f"(c[1]), "+f"(c[2]), "+f"(c[3])
        : "r"(a0), "r"(a1), "r"(a2), "r"(a3), "r"(b0), "r"(b1));
}
__device__ __forceinline__ void cp16(uint32_t s, const void* g) {
    asm volatile("cp.async.cg.shared.global [%0], [%1], 16;" :: "r"(s), "l"(g));
}
__device__ __forceinline__ void cp_commit() {
    asm volatile("cp.async.commit_group;" ::: "memory");
}
template<int N> __device__ __forceinline__ void cp_wait() {
    asm volatile("cp.async.wait_group %0;" :: "n"(N) : "memory");
}

// ============================================================
// K1: transpose key_layer [B,C,HW] -> g_key_t [B,HW,C]
// ============================================================
__global__ void k_transpose(const float* __restrict__ key) {
    __shared__ float t[32][33];
    int b   = blockIdx.z;
    int hw0 = blockIdx.x * 32;
    int c0  = blockIdx.y * 32;
    int tx = threadIdx.x, ty = threadIdx.y;
    const float* src = key + (size_t)b * Cn * HWn;
    #pragma unroll
    for (int i = 0; i < 4; i++)
        t[ty + i*8][tx] = src[(size_t)(c0 + ty + i*8) * HWn + hw0 + tx];
    __syncthreads();
    float* dst = g_key_t + (size_t)b * HWn * Cn;
    #pragma unroll
    for (int i = 0; i < 4; i++)
        dst[(size_t)(hw0 + ty + i*8) * Cn + c0 + tx] = t[tx][ty + i*8];
}

// ============================================================
// K2: per-pixel params, split-C across two thread groups.
// Block = 128 pixels; ph = tid>>7 handles C-half; smem reduce; softmaxes by ph0.
// ============================================================
__global__ void __launch_bounds__(256)
k_params(const float* __restrict__ query,
         const float* __restrict__ gmb,
         const float* __restrict__ b_attn,
         const float* __restrict__ b_mask,
         const float* __restrict__ b_off,
         const float* __restrict__ w_attn,
         const float* __restrict__ w_mask,
         const float* __restrict__ w_off,
         const unsigned* __restrict__ temp_raw) {
    __shared__ float4 sW[28*64];
    __shared__ float  sB[28];
    __shared__ float  sPart[128*29];   // partial sums, pitch 29 to dodge conflicts
    int tid = threadIdx.x;
    for (int i = tid; i < 576; i += 256) sW[i]        = ((const float4*)w_attn)[i];
    for (int i = tid; i < 576; i += 256) sW[576 + i]  = ((const float4*)w_mask)[i];
    for (int i = tid; i < 640; i += 256) sW[1152 + i] = ((const float4*)w_off)[i];
    if (tid < 9)  { sB[tid] = b_attn[tid]; sB[9 + tid] = b_mask[tid]; }
    if (tid < 10) sB[18 + tid] = b_off[tid];
    __syncthreads();

    int lp = tid & 127, ph = tid >> 7;
    int pix = blockIdx.x * 128 + lp;
    int b  = pix >> 12;
    int hw = pix & (HWn - 1);

    const float* q = query + (size_t)b * Cn * HWn + (size_t)(ph*128) * HWn + hw;
    float acc[28];
    #pragma unroll
    for (int r = 0; r < 28; r++) acc[r] = 0.f;

    #pragma unroll 4
    for (int c4 = 0; c4 < 32; c4++) {
        float q0 = q[(c4*4 + 0) * HWn];
        float q1 = q[(c4*4 + 1) * HWn];
        float q2 = q[(c4*4 + 2) * HWn];
        float q3 = q[(c4*4 + 3) * HWn];
        #pragma unroll
        for (int r = 0; r < 28; r++) {
            float4 w = sW[r*64 + ph*32 + c4];
            acc[r] += q0*w.x + q1*w.y + q2*w.z + q3*w.w;
        }
    }

    if (ph == 1) {
        #pragma unroll
        for (int r = 0; r < 28; r++) sPart[lp*29 + r] = acc[r];
    }
    __syncthreads();
    if (ph == 1) return;

    #pragma unroll
    for (int r = 0; r < 28; r++) acc[r] += sPart[lp*29 + r];

    unsigned lo = temp_raw[0];
    float t;
    if      (lo == 1u)           t = 1.f;
    else if (lo == 0x3F800000u)  t = 1.f;
    else if (lo == 0u)           t = 1.f;
    else                         t = __uint_as_float(lo);
    float invt = 1.f / t;

    float mv[9]; float mx = -3.4e38f;
    #pragma unroll
    for (int k = 0; k < 9; k++) {
        float gk = gmb[(size_t)(b*Kn + k) * HWn + hw];
        mv[k] = (acc[9 + k] + sB[9 + k] + gk) * invt;
        mx = fmaxf(mx, mv[k]);
    }
    float sum = 0.f;
    #pragma unroll
    for (int k = 0; k < 9; k++) { mv[k] = expf(mv[k] - mx); sum += mv[k]; }
    float rs = 1.f / sum;

    float z[9]; float mx2 = -3.4e38f;
    #pragma unroll
    for (int k = 0; k < 9; k++) {
        z[k] = (acc[k] + sB[k]) * (mv[k] * rs);
        mx2 = fmaxf(mx2, z[k]);
    }
    float sum2 = 0.f;
    #pragma unroll
    for (int k = 0; k < 9; k++) { z[k] = expf(z[k] - mx2); sum2 += z[k]; }
    float rs2 = 1.f / sum2;

    #pragma unroll
    for (int k = 0; k < 9; k++) {
        int o = (b*Kn + k) * HWn + hw;
        g_aw[o] = z[k] * rs2;
        g_dy[o] = acc[18 + k] + sB[18 + k];
        g_dx[o] = acc[19 + k] + sB[19 + k];
    }
}

// ============================================================
// K3: split w_refer into bf16 hi/lo
// ============================================================
__global__ void k_wsplit(const float* __restrict__ w) {
    int i = blockIdx.x * 256 + threadIdx.x;
    float v = w[i];
    __nv_bfloat16 h = __float2bfloat16(v);
    g_wh[i] = h;
    g_wl[i] = __float2bfloat16(v - __bfloat162float(h));
}

// ============================================================
// K4: gather with tap dedup, tap-count padded to x4 for unrolled
//     high-MLP channel loop; outputs s as bf16 hi/lo.
// ============================================================
__global__ void k_gather() {
    __shared__ int   s_idx[64][40];
    __shared__ float s_w[64][40];
    __shared__ int   s_cnt[64];
    int y   = blockIdx.x;
    int b   = blockIdx.y;
    int tid = threadIdx.x;

    if (tid < 64) {
        int p = tid, hw = y*Wn + p;
        float gs = 0.f; int n = 0;
        #pragma unroll
        for (int k = 0; k < 9; k++) {
            int o = (b*Kn + k) * HWn + hw;
            float aw = g_aw[o];
            float dy = g_dy[o], dx = g_dx[o];
            float py = (float)y + dy;
            float px = (float)p + dx;
            float y0f = floorf(py), x0f = floorf(px);
            float wy = py - y0f, wx = px - x0f;
            int y0 = (int)y0f, x0 = (int)x0f;
            float ws[4] = {(1.f-wy)*(1.f-wx), (1.f-wy)*wx, wy*(1.f-wx), wy*wx};
            int   yy[4] = {y0, y0, y0+1, y0+1};
            int   xx[4] = {x0, x0+1, x0, x0+1};
            #pragma unroll
            for (int t = 0; t < 4; t++) {
                bool v = (yy[t] >= 0) & (yy[t] < Hn) & (xx[t] >= 0) & (xx[t] < Wn);
                float w = ws[t] * aw;
                if (!v || w == 0.f) continue;
                int idx = (yy[t]*Wn + xx[t]) * Cn;
                gs += w;
                int j = 0;
                for (; j < n; j++)
                    if (s_idx[p][j] == idx) { s_w[p][j] += w; break; }
                if (j == n) { s_idx[p][n] = idx; s_w[p][n] = w; n++; }
            }
        }
        int n4 = (n + 3) & ~3;           // pad to multiple of 4
        for (int j = n; j < n4; j++) { s_idx[p][j] = 0; s_w[p][j] = 0.f; }
        s_cnt[p] = n4;
        g_g[b*HWn + hw] = gs;
    }
    __syncthreads();

    int c4 = tid & 63;          // float4 channel group
    int pg = tid >> 6;          // pixel phase (0..3)
    const float4* kb = (const float4*)(g_key_t + (size_t)b * HWn * Cn);
    for (int p = pg; p < 64; p += 4) {
        int n4 = s_cnt[p];
        float4 a0 = make_float4(0.f,0.f,0.f,0.f);
        float4 a1 = a0, a2 = a0, a3 = a0;
        for (int j = 0; j < n4; j += 4) {
            float w0 = s_w[p][j+0]; int i0 = s_idx[p][j+0];
            float w1 = s_w[p][j+1]; int i1 = s_idx[p][j+1];
            float w2 = s_w[p][j+2]; int i2 = s_idx[p][j+2];
            float w3 = s_w[p][j+3]; int i3 = s_idx[p][j+3];
            float4 v0 = kb[(i0 >> 2) + c4];
            float4 v1 = kb[(i1 >> 2) + c4];
            float4 v2 = kb[(i2 >> 2) + c4];
            float4 v3 = kb[(i3 >> 2) + c4];
            a0.x += w0*v0.x; a0.y += w0*v0.y; a0.z += w0*v0.z; a0.w += w0*v0.w;
            a1.x += w1*v1.x; a1.y += w1*v1.y; a1.z += w1*v1.z; a1.w += w1*v1.w;
            a2.x += w2*v2.x; a2.y += w2*v2.y; a2.z += w2*v2.z; a2.w += w2*v2.w;
            a3.x += w3*v3.x; a3.y += w3*v3.y; a3.z += w3*v3.z; a3.w += w3*v3.w;
        }
        float4 acc;
        acc.x = (a0.x + a1.x) + (a2.x + a3.x);
        acc.y = (a0.y + a1.y) + (a2.y + a3.y);
        acc.z = (a0.z + a1.z) + (a2.z + a3.z);
        acc.w = (a0.w + a1.w) + (a2.w + a3.w);

        size_t base = ((size_t)(b*HWn + y*Wn + p)) * Cn + c4*4;
        __nv_bfloat16 hx = __float2bfloat16(acc.x);
        __nv_bfloat16 hy = __float2bfloat16(acc.y);
        __nv_bfloat16 hz = __float2bfloat16(acc.z);
        __nv_bfloat16 hw4 = __float2bfloat16(acc.w);
        __nv_bfloat16 lx = __float2bfloat16(acc.x - __bfloat162float(hx));
        __nv_bfloat16 ly = __float2bfloat16(acc.y - __bfloat162float(hy));
        __nv_bfloat16 lz = __float2bfloat16(acc.z - __bfloat162float(hz));
        __nv_bfloat16 lw = __float2bfloat16(acc.w - __bfloat162float(hw4));
        __nv_bfloat162 h0 = __halves2bfloat162(hx, hy);
        __nv_bfloat162 h1 = __halves2bfloat162(hz, hw4);
        __nv_bfloat162 l0 = __halves2bfloat162(lx, ly);
        __nv_bfloat162 l1 = __halves2bfloat162(lz, lw);
        uint2 uh, ul;
        uh.x = *(uint32_t*)&h0; uh.y = *(uint32_t*)&h1;
        ul.x = *(uint32_t*)&l0; ul.y = *(uint32_t*)&l1;
        *(uint2*)&g_sh[base] = uh;
        *(uint2*)&g_sl[base] = ul;
    }
}

// ============================================================
// K5: mma.sync bf16 split GEMM with 3-stage cp.async pipeline
//   D[o,p] = Wh.Sh^T + Wl.Sh^T + Wh.Sl^T  (virtual K = 768)
//   CTA 128x128, 8 warps (2x4), warp 64x32, k-chunk 32.
// SMEM pitch 80B -> conflict-free ldmatrix.
// ============================================================
#define PITCH_B 80
#define TILE_B  (128*PITCH_B)       // 10240 B per operand tile
#define NCHUNK  24                  // 3 segments * 8 chunks
#define GEMM_SMEM (3*2*TILE_B)      // 61440 B

__global__ void __launch_bounds__(256)
k_gemm_mma(const float* __restrict__ bref, float* __restrict__ out) {
    extern __shared__ __align__(16) char gsm[];
    int tid = threadIdx.x, wid = tid >> 5, lane = tid & 31;
    int p0 = blockIdx.x * 128;
    int o0 = blockIdx.y * 128;
    int bz = blockIdx.z;
    int wr = wid >> 2;          // 0..1 (m)
    int wn = wid & 3;           // 0..3 (n)

    const __nv_bfloat16* Aseg[3] = {g_wh, g_wl, g_wh};
    const __nv_bfloat16* Bseg[3] = {g_sh, g_sh, g_sl};
    uint32_t sbase = smem_u32(gsm);

    int rA = tid >> 2;          // 0..63: copy rows rA and rA+64
    int pa = (tid & 3) * 16;    // 16B part within the 64B row

    float acc[4][4][4];
    #pragma unroll
    for (int i = 0; i < 4; i++)
        #pragma unroll
        for (int j = 0; j < 4; j++)
            #pragma unroll
            for (int r = 0; r < 4; r++) acc[i][j][r] = 0.f;

    int lm_row = ((lane >> 3) & 1) * 8 + (lane & 7);
    int lm_col = (lane >> 4) * 16;
    int bn_row = lane >> 2;
    int bn_col = (lane & 3) * 4;

#define ISSUE(CH) do { \
        int _st = (CH) % 3, _seg = (CH) >> 3, _c0 = ((CH) & 7) * 32; \
        const char* _Ag = (const char*)(Aseg[_seg] + (size_t)o0*Cn + _c0) \
                          + (size_t)rA*(Cn*2) + pa; \
        const char* _Bg = (const char*)(Bseg[_seg] + ((size_t)bz*HWn + p0)*Cn + _c0) \
                          + (size_t)rA*(Cn*2) + pa; \
        uint32_t _sa = sbase + _st*(2*TILE_B); \
        uint32_t _sb = _sa + TILE_B; \
        cp16(_sa + rA*PITCH_B + pa,        _Ag); \
        cp16(_sa + (rA+64)*PITCH_B + pa,   _Ag + 64*(Cn*2)); \
        cp16(_sb + rA*PITCH_B + pa,        _Bg); \
        cp16(_sb + (rA+64)*PITCH_B + pa,   _Bg + 64*(Cn*2)); \
        cp_commit(); \
    } while (0)

    ISSUE(0);
    ISSUE(1);

    for (int ch = 0; ch < NCHUNK; ch++) {
        if (ch == NCHUNK - 1) cp_wait<0>(); else cp_wait<1>();
        __syncthreads();
        if (ch + 2 < NCHUNK) ISSUE(ch + 2);

        uint32_t sa = sbase + (ch % 3)*(2*TILE_B);
        uint32_t sb = sa + TILE_B;
        #pragma unroll
        for (int ks = 0; ks < 2; ks++) {
            uint32_t bf[4][2];
            #pragma unroll
            for (int nt = 0; nt < 4; nt++) {
                uint32_t ba = sb + (wn*32 + nt*8 + bn_row)*PITCH_B + bn_col + ks*32;
                bf[nt][0] = lds32(ba);
                bf[nt][1] = lds32(ba + 16);
            }
            #pragma unroll
            for (int mt = 0; mt < 4; mt++) {
                uint32_t a0, a1, a2, a3;
                uint32_t aa = sa + (wr*64 + mt*16 + lm_row)*PITCH_B + lm_col + ks*32;
                ldmatrix_x4(a0, a1, a2, a3, aa);
                #pragma unroll
                for (int nt = 0; nt < 4; nt++)
                    mma16816(acc[mt][nt], a0, a1, a2, a3, bf[nt][0], bf[nt][1]);
            }
        }
    }
#undef ISSUE

    // ---- epilogue ----
    int mrow = lane >> 2;          // 0..7
    int ncol = (lane & 3) * 2;     // 0,2,4,6
    #pragma unroll
    for (int mt = 0; mt < 4; mt++) {
        int o = o0 + wr*64 + mt*16 + mrow;
        float bb0 = bref[o], bb1 = bref[o + 8];
        #pragma unroll
        for (int nt = 0; nt < 4; nt++) {
            int p = p0 + wn*32 + nt*8 + ncol;
            float2 gg = *(const float2*)&g_g[bz*HWn + p];
            float2 r0, r1;
            r0.x = acc[mt][nt][0] + bb0*gg.x;
            r0.y = acc[mt][nt][1] + bb0*gg.y;
            r1.x = acc[mt][nt][2] + bb1*gg.x;
            r1.y = acc[mt][nt][3] + bb1*gg.y;
            *(float2*)&out[((size_t)(bz*Cn + o))     * HWn + p] = r0;
            *(float2*)&out[((size_t)(bz*Cn + o + 8)) * HWn + p] = r1;
        }
    }
}

// ============================================================
extern "C" void kernel_launch(void* const* d_in, const int* in_sizes, int n_in,
                              void* d_out, int out_size) {
    const float* query   = (const float*)d_in[0];
    const float* key     = (const float*)d_in[1];
    const float* gmb     = (const float*)d_in[2];
    const float* w_refer = (const float*)d_in[3];
    const float* b_refer = (const float*)d_in[4];
    const float* w_attn  = (const float*)d_in[5];
    const float* b_attn  = (const float*)d_in[6];
    const float* w_mask  = (const float*)d_in[7];
    const float* b_mask  = (const float*)d_in[8];
    const float* w_off   = (const float*)d_in[9];
    const float* b_off   = (const float*)d_in[10];
    const unsigned* temp = (const unsigned*)d_in[11];
    float* out = (float*)d_out;

    static int attr_set = 0;
    if (!attr_set) {
        cudaFuncSetAttribute(k_gemm_mma, cudaFuncAttributeMaxDynamicSharedMemorySize,
                             GEMM_SMEM);
        attr_set = 1;
    }

    k_transpose<<<dim3(HWn/32, Cn/32, Bn), dim3(32, 8)>>>(key);
    k_params<<<NPIX/128, 256>>>(query, gmb, b_attn, b_mask, b_off,
                                w_attn, w_mask, w_off, temp);
    k_wsplit<<<Cn*Cn/256, 256>>>(w_refer);
    k_gather<<<dim3(Hn, Bn), 256>>>();
    k_gemm_mma<<<dim3(HWn/128, Cn/128, Bn), 256, GEMM_SMEM>>>(b_refer, out);
}